// round 5
// baseline (speedup 1.0000x reference)
#include <cuda_runtime.h>

#define BB 16
#define TT 96
#define TP1 97
#define HW 16384
#define NSTEP 6
#define MTHR 0.9f

// ---- scratch (device globals; no allocation APIs) ----
__device__ float         g_D[(size_t)BB * HW * TT];  // d[b][p][t], t contiguous (~100MB)
__device__ double        g_delta[BB * TP1];          // idx0 = empty template, always 0
__device__ unsigned char g_topcov[BB * HW];
__device__ float         g_topval[BB * HW];
__device__ int           g_hist[NSTEP * BB];         // selected cid per (step, batch)
__device__ int           g_cnt[NSTEP * BB];          // new-pixel count per (step, batch)
__device__ int           g_list[NSTEP * BB * HW];    // new-pixel indices (~6MB)

// ---------------------------------------------------------------------------
__global__ void k_init() {
    int i = threadIdx.x;
    for (int j = i; j < BB * TP1; j += 256) g_delta[j] = 0.0;
    if (i < NSTEP * BB) g_cnt[i] = 0;
}

// ---------------------------------------------------------------------------
// Precompute D[b][p][t] = cov ? (x - t*m)^2 - (x - bg)^2 : 0, plus delta0[b][t].
// 256 threads per (b, 64-pixel tile); float4 loads, 16 templates per iteration
// (12 x 16B loads in flight per thread). SMEM transpose -> t-contiguous stores.
__global__ void k_precompute(const float* __restrict__ x,
                             const float* __restrict__ temps,
                             const float* __restrict__ msks,
                             const float* __restrict__ bg) {
    __shared__ float xs[64], eb[64];
    __shared__ float dsm[64][TP1];   // stride 97: conflict-light rows & columns

    const int b   = blockIdx.y;
    const int p0  = blockIdx.x * 64;
    const int tid = threadIdx.x;

    if (tid < 64) {
        float xv = x[b * HW + p0 + tid];
        float bv = bg[p0 + tid];
        xs[tid] = xv;
        float e = xv - bv;
        eb[tid] = e * e;
        g_topcov[b * HW + p0 + tid] = 0;   // fold init here
    }
    __syncthreads();

    const int ts  = tid >> 4;    // 0..15 -> sixteen templates per iteration
    const int ps4 = tid & 15;    // float4 index: pixels 4*ps4 .. 4*ps4+3
    #pragma unroll
    for (int t16 = 0; t16 < TT; t16 += 16) {
        int t = t16 + ts;
        const size_t rb = (size_t)(b * TT + t) * HW + p0;
        float4 tv = __ldg((const float4*)(temps + rb) + ps4);
        float4 mv = __ldg((const float4*)(msks  + rb) + ps4);
        int p = 4 * ps4;
        float d0 = 0.f, d1 = 0.f, d2 = 0.f, d3 = 0.f;
        if (mv.x > MTHR) { float a = xs[p]     - tv.x * mv.x; d0 = a * a - eb[p];     }
        if (mv.y > MTHR) { float a = xs[p + 1] - tv.y * mv.y; d1 = a * a - eb[p + 1]; }
        if (mv.z > MTHR) { float a = xs[p + 2] - tv.z * mv.z; d2 = a * a - eb[p + 2]; }
        if (mv.w > MTHR) { float a = xs[p + 3] - tv.w * mv.w; d3 = a * a - eb[p + 3]; }
        dsm[p][t]     = d0;
        dsm[p + 1][t] = d1;
        dsm[p + 2][t] = d2;
        dsm[p + 3][t] = d3;
    }
    __syncthreads();

    // store D with float4 (6144 floats per tile, fully contiguous)
    const size_t obase = ((size_t)b * HW + p0) * TT;
    for (int i = tid; i < 64 * TT / 4; i += 256) {
        int r = i / 24, c = (i % 24) * 4;
        float4 v = make_float4(dsm[r][c], dsm[r][c + 1], dsm[r][c + 2], dsm[r][c + 3]);
        *(float4*)&g_D[obase + (size_t)i * 4] = v;
    }

    // per-t partial sums -> delta0
    if (tid < TT) {
        float s = 0.f;
        #pragma unroll
        for (int p = 0; p < 64; p++) s += dsm[p][tid];
        atomicAdd(&g_delta[b * TP1 + 1 + tid], (double)s);
    }
}

// ---------------------------------------------------------------------------
// One greedy step: every block recomputes argmin (deterministic, redundant),
// paints its 256 pixels, appends newly covered pixels to the step list.
// On the last step, also writes the final composition for its pixels.
__global__ void k_paint(int s, int last,
                        const float* __restrict__ temps,
                        const float* __restrict__ msks,
                        const float* __restrict__ bg,
                        float* __restrict__ out) {
    __shared__ int s_cid;
    const int b   = blockIdx.y;
    const int tid = threadIdx.x;

    if (tid < 32) {
        double bestv = 1e300;
        int    besti = TP1;
        for (int t = tid; t < TP1; t += 32) {
            double v = g_delta[b * TP1 + t];
            for (int j = 0; j < s; j++)
                if (g_hist[j * BB + b] == t && t != 0) v = 1e30;  // used penalty
            if (v < bestv) { bestv = v; besti = t; }              // earliest on tie
        }
        for (int off = 16; off; off >>= 1) {
            double ov = __shfl_down_sync(0xffffffffu, bestv, off);
            int    oi = __shfl_down_sync(0xffffffffu, besti, off);
            if (ov < bestv || (ov == bestv && oi < besti)) { bestv = ov; besti = oi; }
        }
        if (tid == 0) {
            s_cid = besti;
            if (blockIdx.x == 0) g_hist[s * BB + b] = besti;
        }
    }
    __syncthreads();

    const int cid = s_cid;
    const int p   = blockIdx.x * 256 + tid;
    const int q   = b * HW + p;

    bool nw = false;
    if (cid != 0) {
        const int idx = (b * TT + cid - 1) * HW + p;
        float mv = msks[idx];
        if (mv > MTHR && !g_topcov[q]) {
            g_topval[q] = temps[idx] * mv;   // new object goes UNDER existing
            g_topcov[q] = 1;
            nw = true;
        }
    }

    if (!last) {
        // warp-aggregated append of new pixels to this step's list
        unsigned m = __ballot_sync(0xffffffffu, nw);
        if (m) {
            int lane   = tid & 31;
            int leader = __ffs(m) - 1;
            int base = 0;
            if (lane == leader) base = atomicAdd(&g_cnt[s * BB + b], __popc(m));
            base = __shfl_sync(0xffffffffu, base, leader);
            if (nw) g_list[(s * BB + b) * HW + base + __popc(m & ((1u << lane) - 1))] = p;
        }
    } else {
        out[q] = g_topcov[q] ? g_topval[q] : bg[p];
    }
}

// ---------------------------------------------------------------------------
// delta[b][t] -= sum over this step's new pixels of D[b][p][t].
// Grid (16, BB): each block takes a contiguous ~cnt/16 slice of the list,
// loads all indices with ONE sync, then streams fully independent gathers.
__global__ void __launch_bounds__(128) k_sub(int s) {
    const int b   = blockIdx.y;
    const int cnt = g_cnt[s * BB + b];
    if (cnt == 0) return;
    const int per = (cnt + gridDim.x - 1) / gridDim.x;
    const int lo  = blockIdx.x * per;
    if (lo >= cnt) return;
    const int n   = min(per, cnt - lo);
    const int t   = threadIdx.x;

    __shared__ int sl[1024];
    float a0=0,a1=0,a2=0,a3=0,a4=0,a5=0,a6=0,a7=0;

    for (int base = 0; base < n; base += 1024) {
        const int m = min(1024, n - base);
        for (int j = t; j < m; j += 128)
            sl[j] = g_list[(s * BB + b) * HW + lo + base + j];
        __syncthreads();
        if (t < TT) {
            const float* Db = g_D + (size_t)b * HW * TT + t;
            int j = 0;
            for (; j + 8 <= m; j += 8) {
                a0 += Db[(size_t)sl[j    ] * TT];
                a1 += Db[(size_t)sl[j + 1] * TT];
                a2 += Db[(size_t)sl[j + 2] * TT];
                a3 += Db[(size_t)sl[j + 3] * TT];
                a4 += Db[(size_t)sl[j + 4] * TT];
                a5 += Db[(size_t)sl[j + 5] * TT];
                a6 += Db[(size_t)sl[j + 6] * TT];
                a7 += Db[(size_t)sl[j + 7] * TT];
            }
            for (; j < m; j++) a0 += Db[(size_t)sl[j] * TT];
        }
        __syncthreads();
    }
    if (t < TT) {
        float tot = ((a0 + a1) + (a2 + a3)) + ((a4 + a5) + (a6 + a7));
        atomicAdd(&g_delta[b * TP1 + 1 + t], -(double)tot);
    }
}

// ---------------------------------------------------------------------------
extern "C" void kernel_launch(void* const* d_in, const int* in_sizes, int n_in,
                              void* d_out, int out_size) {
    const float* x      = (const float*)d_in[0];   // (16,1,128,128)
    const float* temps  = (const float*)d_in[1];   // (16,96,1,128,128)
    const float* msks   = (const float*)d_in[2];   // (16,96,1,128,128)
    const float* bg     = (const float*)d_in[3];   // (1,128,128)
    float* out = (float*)d_out;                    // (16,1,128,128)

    k_init<<<1, 256>>>();
    k_precompute<<<dim3(HW / 64, BB), 256>>>(x, temps, msks, bg);

    for (int s = 0; s < NSTEP; s++) {
        int last = (s == NSTEP - 1);
        k_paint<<<dim3(HW / 256, BB), 256>>>(s, last, temps, msks, bg, out);
        if (!last) k_sub<<<dim3(16, BB), 128>>>(s);
    }
}

// round 6
// speedup vs baseline: 1.1179x; 1.1179x over previous
#include <cuda_runtime.h>

#define BB 16
#define TT 96
#define TP1 97
#define HW 16384
#define NSTEP 6
#define MTHR 0.9f

// ---- scratch (device globals; no allocation APIs) ----
__device__ float         g_D[(size_t)BB * HW * TT];  // d[b][p][t], t contiguous (~100MB)
__device__ double        g_delta[BB * TP1];          // idx0 = empty template, always 0
__device__ unsigned char g_topcov[BB * HW];
__device__ float         g_topval[BB * HW];
__device__ int           g_hist[NSTEP * BB];         // selected cid per (step, batch)
__device__ int           g_cnt[NSTEP * BB];          // new-pixel count per (step, batch)
__device__ int           g_list[NSTEP * BB * HW];    // new-pixel indices (~6MB)

// ---------------------------------------------------------------------------
__global__ void k_init() {
    int i = threadIdx.x;
    for (int j = i; j < BB * TP1; j += 256) g_delta[j] = 0.0;
    if (i < NSTEP * BB) g_cnt[i] = 0;
}

// ---------------------------------------------------------------------------
// Precompute D[b][p][t] = cov ? (x - t*m)^2 - (x - bg)^2 : 0, plus delta0[b][t].
// 256 threads per (b, 64-pixel tile); float4 loads, 16 templates per iteration.
__global__ void k_precompute(const float* __restrict__ x,
                             const float* __restrict__ temps,
                             const float* __restrict__ msks,
                             const float* __restrict__ bg) {
    __shared__ float xs[64], eb[64];
    __shared__ float dsm[64][TP1];   // stride 97: conflict-light rows & columns

    const int b   = blockIdx.y;
    const int p0  = blockIdx.x * 64;
    const int tid = threadIdx.x;

    if (tid < 64) {
        float xv = x[b * HW + p0 + tid];
        float bv = bg[p0 + tid];
        xs[tid] = xv;
        float e = xv - bv;
        eb[tid] = e * e;
        g_topcov[b * HW + p0 + tid] = 0;   // fold init here
    }
    __syncthreads();

    const int ts  = tid >> 4;    // 0..15 -> sixteen templates per iteration
    const int ps4 = tid & 15;    // float4 index: pixels 4*ps4 .. 4*ps4+3
    #pragma unroll
    for (int t16 = 0; t16 < TT; t16 += 16) {
        int t = t16 + ts;
        const size_t rb = (size_t)(b * TT + t) * HW + p0;
        float4 tv = __ldg((const float4*)(temps + rb) + ps4);
        float4 mv = __ldg((const float4*)(msks  + rb) + ps4);
        int p = 4 * ps4;
        float d0 = 0.f, d1 = 0.f, d2 = 0.f, d3 = 0.f;
        if (mv.x > MTHR) { float a = xs[p]     - tv.x * mv.x; d0 = a * a - eb[p];     }
        if (mv.y > MTHR) { float a = xs[p + 1] - tv.y * mv.y; d1 = a * a - eb[p + 1]; }
        if (mv.z > MTHR) { float a = xs[p + 2] - tv.z * mv.z; d2 = a * a - eb[p + 2]; }
        if (mv.w > MTHR) { float a = xs[p + 3] - tv.w * mv.w; d3 = a * a - eb[p + 3]; }
        dsm[p][t]     = d0;
        dsm[p + 1][t] = d1;
        dsm[p + 2][t] = d2;
        dsm[p + 3][t] = d3;
    }
    __syncthreads();

    // store D with float4 (6144 floats per tile, fully contiguous)
    const size_t obase = ((size_t)b * HW + p0) * TT;
    for (int i = tid; i < 64 * TT / 4; i += 256) {
        int r = i / 24, c = (i % 24) * 4;
        float4 v = make_float4(dsm[r][c], dsm[r][c + 1], dsm[r][c + 2], dsm[r][c + 3]);
        *(float4*)&g_D[obase + (size_t)i * 4] = v;
    }

    // per-t partial sums -> delta0
    if (tid < TT) {
        float s = 0.f;
        #pragma unroll
        for (int p = 0; p < 64; p++) s += dsm[p][tid];
        atomicAdd(&g_delta[b * TP1 + 1 + tid], (double)s);
    }
}

// ---------------------------------------------------------------------------
// One greedy step: every block recomputes argmin (deterministic, redundant),
// paints its 256 pixels, appends newly covered pixels to the step list.
// On the last step, also writes the final composition for its pixels.
__global__ void k_paint(int s, int last,
                        const float* __restrict__ temps,
                        const float* __restrict__ msks,
                        const float* __restrict__ bg,
                        float* __restrict__ out) {
    __shared__ int s_cid;
    const int b   = blockIdx.y;
    const int tid = threadIdx.x;

    if (tid < 32) {
        double bestv = 1e300;
        int    besti = TP1;
        for (int t = tid; t < TP1; t += 32) {
            double v = g_delta[b * TP1 + t];
            for (int j = 0; j < s; j++)
                if (g_hist[j * BB + b] == t && t != 0) v = 1e30;  // used penalty
            if (v < bestv) { bestv = v; besti = t; }              // earliest on tie
        }
        for (int off = 16; off; off >>= 1) {
            double ov = __shfl_down_sync(0xffffffffu, bestv, off);
            int    oi = __shfl_down_sync(0xffffffffu, besti, off);
            if (ov < bestv || (ov == bestv && oi < besti)) { bestv = ov; besti = oi; }
        }
        if (tid == 0) {
            s_cid = besti;
            if (blockIdx.x == 0) g_hist[s * BB + b] = besti;
        }
    }
    __syncthreads();

    const int cid = s_cid;
    const int p   = blockIdx.x * 256 + tid;
    const int q   = b * HW + p;

    bool nw = false;
    if (cid != 0) {
        const int idx = (b * TT + cid - 1) * HW + p;
        float mv = msks[idx];
        if (mv > MTHR && !g_topcov[q]) {
            g_topval[q] = temps[idx] * mv;   // new object goes UNDER existing
            g_topcov[q] = 1;
            nw = true;
        }
    }

    if (!last) {
        // warp-aggregated append of new pixels to this step's list
        unsigned m = __ballot_sync(0xffffffffu, nw);
        if (m) {
            int lane   = tid & 31;
            int leader = __ffs(m) - 1;
            int base = 0;
            if (lane == leader) base = atomicAdd(&g_cnt[s * BB + b], __popc(m));
            base = __shfl_sync(0xffffffffu, base, leader);
            if (nw) g_list[(s * BB + b) * HW + base + __popc(m & ((1u << lane) - 1))] = p;
        }
    } else {
        out[q] = g_topcov[q] ? g_topval[q] : bg[p];
    }
}

// ---------------------------------------------------------------------------
// delta[b][t] -= sum over this step's new pixels of D[b][p][t].
// Warp-autonomous: each warp owns one 32-pixel chunk (grid-stride over chunks).
// Lane l gathers t = 3l..3l+2 of each pixel row (384B rows, sector-coalesced).
// No shared memory, no __syncthreads; 96 independent loads in flight per lane.
__global__ void __launch_bounds__(128) k_sub(int s) {
    const int b   = blockIdx.y;
    const int cnt = g_cnt[s * BB + b];
    if (cnt == 0) return;
    const int nch    = (cnt + 31) >> 5;
    const int lane   = threadIdx.x & 31;
    const int warp   = blockIdx.x * 4 + (threadIdx.x >> 5);   // 0..127 per batch
    const int nwarps = gridDim.x * 4;

    const float* __restrict__ Db = g_D + (size_t)b * HW * TT + lane * 3;
    float a0 = 0.f, a1 = 0.f, a2 = 0.f;
    bool any = false;

    for (int c = warp; c < nch; c += nwarps) {
        const int base = c * 32;
        const int nrem = min(32, cnt - base);
        int myidx = (lane < nrem) ? g_list[(s * BB + b) * HW + base + lane] : -1;
        any = true;
        #pragma unroll
        for (int j = 0; j < 32; j++) {
            int idx = __shfl_sync(0xffffffffu, myidx, j);
            if (idx >= 0) {
                const float* row = Db + (size_t)idx * TT;
                a0 += row[0];
                a1 += row[1];
                a2 += row[2];
            }
        }
    }
    if (any) {
        double* dd = &g_delta[b * TP1 + 1 + lane * 3];
        if (a0 != 0.f) atomicAdd(dd,     -(double)a0);
        if (a1 != 0.f) atomicAdd(dd + 1, -(double)a1);
        if (a2 != 0.f) atomicAdd(dd + 2, -(double)a2);
    }
}

// ---------------------------------------------------------------------------
extern "C" void kernel_launch(void* const* d_in, const int* in_sizes, int n_in,
                              void* d_out, int out_size) {
    const float* x      = (const float*)d_in[0];   // (16,1,128,128)
    const float* temps  = (const float*)d_in[1];   // (16,96,1,128,128)
    const float* msks   = (const float*)d_in[2];   // (16,96,1,128,128)
    const float* bg     = (const float*)d_in[3];   // (1,128,128)
    float* out = (float*)d_out;                    // (16,1,128,128)

    k_init<<<1, 256>>>();
    k_precompute<<<dim3(HW / 64, BB), 256>>>(x, temps, msks, bg);

    for (int s = 0; s < NSTEP; s++) {
        int last = (s == NSTEP - 1);
        k_paint<<<dim3(HW / 256, BB), 256>>>(s, last, temps, msks, bg, out);
        if (!last) k_sub<<<dim3(32, BB), 128>>>(s);
    }
}

// round 7
// speedup vs baseline: 1.1277x; 1.0087x over previous
#include <cuda_runtime.h>

#define BB 16
#define TT 96
#define TP1 97
#define HW 16384
#define NSTEP 6
#define MTHR 0.9f
#define NBLK 256
#define PXB 1024            // pixels owned per block in the step phase

// ---- scratch (device globals; no allocation APIs) ----
__device__ float         g_D[(size_t)BB * HW * TT];  // d[b][p][t], t contiguous (~100MB)
__device__ double        g_delta[BB * TP1];          // idx0 = empty template, always 0
__device__ unsigned char g_topcov[BB * HW];
__device__ float         g_topval[BB * HW];
__device__ int           g_bcnt[8];                  // barrier arrival counters (self-resetting)
__device__ int           g_bgen[8];                  // barrier generations (monotonic)

// ---------------------------------------------------------------------------
__global__ void k_init() {
    int i = threadIdx.x;
    for (int j = i; j < BB * TP1; j += 256) g_delta[j] = 0.0;
}

// ---------------------------------------------------------------------------
// Grid-wide sense-reversing barrier. Counter resets before gen bump, gen is
// monotonic across launches (safe for graph replays). All NBLK blocks must be
// co-resident (guaranteed: 2 blocks/SM fit easily, NBLK=256 <= 2*148).
__device__ __forceinline__ void grid_barrier(int slot) {
    __syncthreads();
    __threadfence();
    if (threadIdx.x == 0) {
        int g   = atomicAdd(&g_bgen[slot], 0);
        int old = atomicAdd(&g_bcnt[slot], 1);
        if (old == NBLK - 1) {
            g_bcnt[slot] = 0;
            __threadfence();
            atomicExch(&g_bgen[slot], g + 1);
        } else {
            while (atomicAdd(&g_bgen[slot], 0) == g) __nanosleep(64);
        }
    }
    __syncthreads();
    __threadfence();
}

// ---------------------------------------------------------------------------
struct SmemPre { float xs[64]; float eb[64]; float dsm[64][TP1]; };
struct SmemStep { int list[PXB]; float partial[2][TT]; unsigned wm[8]; int scid; };
union SmemU { SmemPre pre; SmemStep st; };

__global__ void __launch_bounds__(256, 2)
k_all(const float* __restrict__ x,
      const float* __restrict__ temps,
      const float* __restrict__ msks,
      const float* __restrict__ bg,
      float* __restrict__ out) {
    __shared__ SmemU sm;
    __shared__ unsigned char used[TP1];

    const int tid = threadIdx.x;
    const int blk = blockIdx.x;

    if (tid < TP1) used[tid] = 0;

    // ============ Phase A: precompute D + delta0 (grid-stride, 16 tiles) ====
    for (int tile = blk; tile < BB * (HW / 64); tile += NBLK) {
        const int b  = tile >> 8;            // 256 tiles per batch
        const int p0 = (tile & 255) * 64;

        if (tid < 64) {
            float xv = x[b * HW + p0 + tid];
            float bv = bg[p0 + tid];
            sm.pre.xs[tid] = xv;
            float e = xv - bv;
            sm.pre.eb[tid] = e * e;
            g_topcov[b * HW + p0 + tid] = 0;
        }
        __syncthreads();

        const int ts  = tid >> 4;            // 16 templates per iteration
        const int ps4 = tid & 15;            // float4 pixel group
        #pragma unroll
        for (int t16 = 0; t16 < TT; t16 += 16) {
            int t = t16 + ts;
            const size_t rb = (size_t)(b * TT + t) * HW + p0;
            float4 tv = __ldg((const float4*)(temps + rb) + ps4);
            float4 mv = __ldg((const float4*)(msks  + rb) + ps4);
            int p = 4 * ps4;
            float d0 = 0.f, d1 = 0.f, d2 = 0.f, d3 = 0.f;
            if (mv.x > MTHR) { float a = sm.pre.xs[p]     - tv.x * mv.x; d0 = a * a - sm.pre.eb[p];     }
            if (mv.y > MTHR) { float a = sm.pre.xs[p + 1] - tv.y * mv.y; d1 = a * a - sm.pre.eb[p + 1]; }
            if (mv.z > MTHR) { float a = sm.pre.xs[p + 2] - tv.z * mv.z; d2 = a * a - sm.pre.eb[p + 2]; }
            if (mv.w > MTHR) { float a = sm.pre.xs[p + 3] - tv.w * mv.w; d3 = a * a - sm.pre.eb[p + 3]; }
            sm.pre.dsm[p][t]     = d0;
            sm.pre.dsm[p + 1][t] = d1;
            sm.pre.dsm[p + 2][t] = d2;
            sm.pre.dsm[p + 3][t] = d3;
        }
        __syncthreads();

        const size_t obase = ((size_t)b * HW + p0) * TT;
        for (int i = tid; i < 64 * TT / 4; i += 256) {
            int r = i / 24, c = (i % 24) * 4;
            float4 v = make_float4(sm.pre.dsm[r][c], sm.pre.dsm[r][c + 1],
                                   sm.pre.dsm[r][c + 2], sm.pre.dsm[r][c + 3]);
            *(float4*)&g_D[obase + (size_t)i * 4] = v;
        }

        if (tid < TT) {
            float s = 0.f;
            #pragma unroll
            for (int p = 0; p < 64; p++) s += sm.pre.dsm[p][tid];
            atomicAdd(&g_delta[b * TP1 + 1 + tid], (double)s);
        }
        __syncthreads();   // protect xs/eb/dsm reuse next tile
    }

    grid_barrier(0);

    // ============ Phase B: 6 greedy steps, block owns 1024 pixels ===========
    const int b   = blk >> 4;
    const int p0g = (blk & 15) * PXB;

    for (int s = 0; s < NSTEP; s++) {
        // --- argmin over 97 candidates (redundant per block, identical) ---
        if (tid < 32) {
            double bestv = 1e300;
            int    besti = TP1;
            for (int t = tid; t < TP1; t += 32) {
                double v = __ldcg(&g_delta[b * TP1 + t]);
                if (used[t]) v = 1e30;
                if (v < bestv) { bestv = v; besti = t; }   // earliest on tie
            }
            for (int off = 16; off; off >>= 1) {
                double ov = __shfl_down_sync(0xffffffffu, bestv, off);
                int    oi = __shfl_down_sync(0xffffffffu, besti, off);
                if (ov < bestv || (ov == bestv && oi < besti)) { bestv = ov; besti = oi; }
            }
            if (tid == 0) {
                sm.st.scid = besti;
                if (besti != 0) used[besti] = 1;
            }
        }
        __syncthreads();
        const int cid = sm.st.scid;

        // --- paint own 1024 pixels + deterministic compaction of new ones ---
        int base = 0;                        // block-uniform running count
        if (cid != 0) {
            const size_t mrow = (size_t)(b * TT + cid - 1) * HW;
            for (int k = 0; k < 4; k++) {
                int lp = k * 256 + tid;
                int p  = p0g + lp;
                int q  = b * HW + p;
                bool nw = false;
                float mv = msks[mrow + p];
                if (mv > MTHR && !g_topcov[q]) {
                    g_topval[q] = temps[mrow + p] * mv;  // goes UNDER existing
                    g_topcov[q] = 1;
                    nw = true;
                }
                unsigned m = __ballot_sync(0xffffffffu, nw);
                if ((tid & 31) == 0) sm.st.wm[tid >> 5] = m;
                __syncthreads();
                int off = base, tot = 0;
                #pragma unroll
                for (int w = 0; w < 8; w++) {
                    int c = __popc(sm.st.wm[w]);
                    if (w < (tid >> 5)) off += c;
                    tot += c;
                }
                if (nw) sm.st.list[off + __popc(m & ((1u << (tid & 31)) - 1))] = lp;
                base += tot;
                __syncthreads();
            }
        }
        const int n = base;

        if (s == NSTEP - 1) {
            // --- final composition for own pixels (no subtract needed) ---
            for (int k = 0; k < 4; k++) {
                int p = p0g + k * 256 + tid;
                int q = b * HW + p;
                out[q] = g_topcov[q] ? g_topval[q] : bg[p];
            }
        } else {
            // --- gather-subtract D rows of own new pixels ---
            if (n > 0) {
                const int grp = tid >> 7;    // 0/1: even/odd list entries
                const int lt  = tid & 127;
                float a0 = 0.f, a1 = 0.f, a2 = 0.f, a3 = 0.f;
                if (lt < TT) {
                    const float* Db = g_D + ((size_t)b * HW + p0g) * TT + lt;
                    int j = grp;
                    for (; j + 6 < n; j += 8) {
                        a0 += Db[(size_t)sm.st.list[j    ] * TT];
                        a1 += Db[(size_t)sm.st.list[j + 2] * TT];
                        a2 += Db[(size_t)sm.st.list[j + 4] * TT];
                        a3 += Db[(size_t)sm.st.list[j + 6] * TT];
                    }
                    for (; j < n; j += 2) a0 += Db[(size_t)sm.st.list[j] * TT];
                    sm.st.partial[grp][lt] = (a0 + a1) + (a2 + a3);
                }
                __syncthreads();
                if (tid < TT) {
                    float tot2 = sm.st.partial[0][tid] + sm.st.partial[1][tid];
                    atomicAdd(&g_delta[b * TP1 + 1 + tid], -(double)tot2);
                }
            }
            grid_barrier(1 + s);
        }
    }
}

// ---------------------------------------------------------------------------
extern "C" void kernel_launch(void* const* d_in, const int* in_sizes, int n_in,
                              void* d_out, int out_size) {
    const float* x      = (const float*)d_in[0];   // (16,1,128,128)
    const float* temps  = (const float*)d_in[1];   // (16,96,1,128,128)
    const float* msks   = (const float*)d_in[2];   // (16,96,1,128,128)
    const float* bg     = (const float*)d_in[3];   // (1,128,128)
    float* out = (float*)d_out;                    // (16,1,128,128)

    k_init<<<1, 256>>>();
    k_all<<<NBLK, 256>>>(x, temps, msks, bg, out);
}

// round 8
// speedup vs baseline: 1.5543x; 1.3783x over previous
#include <cuda_runtime.h>

#define BB 16
#define TT 96
#define TP1 97
#define HW 16384
#define NSTEP 6
#define MTHR 0.9f
#define NBLK 512
#define PXB 512             // pixels owned per block (both phases)
#define BPB 32              // blocks per batch

// ---- scratch (device globals; no allocation APIs) ----
__device__ float         g_D[(size_t)BB * HW * TT];  // d[b][p][t], t contiguous (~100MB)
__device__ double        g_delta[BB * TP1];          // idx0 = empty template, always 0
__device__ unsigned char g_topcov[BB * HW];
__device__ float         g_topval[BB * HW];
__device__ int           g_bcnt[8];                  // barrier arrival counters (self-resetting)
__device__ int           g_bgen[8];                  // barrier generations (monotonic)

// ---------------------------------------------------------------------------
__global__ void k_init() {
    int i = threadIdx.x;
    for (int j = i; j < BB * TP1; j += 256) g_delta[j] = 0.0;
}

// ---------------------------------------------------------------------------
// Grid-wide sense-reversing barrier; gen is monotonic (graph-replay safe).
// All NBLK blocks co-resident: 4 blocks/SM * 148 SMs = 592 >= 512.
__device__ __forceinline__ void grid_barrier(int slot) {
    __syncthreads();
    __threadfence();
    if (threadIdx.x == 0) {
        int g   = atomicAdd(&g_bgen[slot], 0);
        int old = atomicAdd(&g_bcnt[slot], 1);
        if (old == NBLK - 1) {
            g_bcnt[slot] = 0;
            __threadfence();
            atomicExch(&g_bgen[slot], g + 1);
        } else {
            while (atomicAdd(&g_bgen[slot], 0) == g) __nanosleep(64);
        }
    }
    __syncthreads();
    __threadfence();
}

// ---------------------------------------------------------------------------
struct SmemPre { float xs[64]; float eb[64]; float dsm[64][TP1]; };
struct SmemStep { int list[PXB]; float partial[2][TT]; unsigned wm[8]; int scid; };
union SmemU { SmemPre pre; SmemStep st; };

__global__ void __launch_bounds__(256, 4)
k_all(const float* __restrict__ x,
      const float* __restrict__ temps,
      const float* __restrict__ msks,
      const float* __restrict__ bg,
      float* __restrict__ out) {
    __shared__ SmemU sm;
    __shared__ float accd[TT];           // per-block delta0 accumulator (phase A)
    __shared__ unsigned char used[TP1];

    const int tid = threadIdx.x;
    const int blk = blockIdx.x;
    const int b   = blk >> 5;            // 32 blocks per batch
    const int p0g = (blk & 31) * PXB;    // block's 512-pixel slice

    if (tid < TP1) used[tid] = 0;
    if (tid < TT)  accd[tid] = 0.f;

    // ============ Phase A: precompute D + delta0 on own 8 tiles =============
    for (int ti = 0; ti < 8; ti++) {
        const int p0 = p0g + ti * 64;

        if (tid < 64) {
            float xv = x[b * HW + p0 + tid];
            float bv = bg[p0 + tid];
            sm.pre.xs[tid] = xv;
            float e = xv - bv;
            sm.pre.eb[tid] = e * e;
            g_topcov[b * HW + p0 + tid] = 0;
        }
        __syncthreads();

        const int ts  = tid >> 4;        // 16 templates per iteration
        const int ps4 = tid & 15;        // float4 pixel group
        #pragma unroll
        for (int t16 = 0; t16 < TT; t16 += 16) {
            int t = t16 + ts;
            const size_t rb = (size_t)(b * TT + t) * HW + p0;
            float4 tv = __ldg((const float4*)(temps + rb) + ps4);
            float4 mv = __ldg((const float4*)(msks  + rb) + ps4);
            int p = 4 * ps4;
            float d0 = 0.f, d1 = 0.f, d2 = 0.f, d3 = 0.f;
            if (mv.x > MTHR) { float a = sm.pre.xs[p]     - tv.x * mv.x; d0 = a * a - sm.pre.eb[p];     }
            if (mv.y > MTHR) { float a = sm.pre.xs[p + 1] - tv.y * mv.y; d1 = a * a - sm.pre.eb[p + 1]; }
            if (mv.z > MTHR) { float a = sm.pre.xs[p + 2] - tv.z * mv.z; d2 = a * a - sm.pre.eb[p + 2]; }
            if (mv.w > MTHR) { float a = sm.pre.xs[p + 3] - tv.w * mv.w; d3 = a * a - sm.pre.eb[p + 3]; }
            sm.pre.dsm[p][t]     = d0;
            sm.pre.dsm[p + 1][t] = d1;
            sm.pre.dsm[p + 2][t] = d2;
            sm.pre.dsm[p + 3][t] = d3;
        }
        __syncthreads();

        const size_t obase = ((size_t)b * HW + p0) * TT;
        for (int i = tid; i < 64 * TT / 4; i += 256) {
            int r = i / 24, c = (i % 24) * 4;
            float4 v = make_float4(sm.pre.dsm[r][c], sm.pre.dsm[r][c + 1],
                                   sm.pre.dsm[r][c + 2], sm.pre.dsm[r][c + 3]);
            *(float4*)&g_D[obase + (size_t)i * 4] = v;
        }

        if (tid < TT) {
            float s = 0.f;
            #pragma unroll
            for (int p = 0; p < 64; p++) s += sm.pre.dsm[p][tid];
            accd[tid] += s;
        }
        __syncthreads();   // protect smem reuse next tile
    }
    if (tid < TT)
        atomicAdd(&g_delta[b * TP1 + 1 + tid], (double)accd[tid]);

    grid_barrier(0);

    // ============ Phase B: 6 greedy steps on own 512 pixels ================
    for (int s = 0; s < NSTEP; s++) {
        // --- argmin over 97 candidates (redundant per block, identical) ---
        if (tid < 32) {
            double bestv = 1e300;
            int    besti = TP1;
            for (int t = tid; t < TP1; t += 32) {
                double v = __ldcg(&g_delta[b * TP1 + t]);
                if (used[t]) v = 1e30;
                if (v < bestv) { bestv = v; besti = t; }   // earliest on tie
            }
            for (int off = 16; off; off >>= 1) {
                double ov = __shfl_down_sync(0xffffffffu, bestv, off);
                int    oi = __shfl_down_sync(0xffffffffu, besti, off);
                if (ov < bestv || (ov == bestv && oi < besti)) { bestv = ov; besti = oi; }
            }
            if (tid == 0) {
                sm.st.scid = besti;
                if (besti != 0) used[besti] = 1;
            }
        }
        __syncthreads();
        const int cid = sm.st.scid;

        // --- paint own pixels + deterministic compaction of new ones ---
        int base = 0;
        if (cid != 0) {
            const size_t mrow = (size_t)(b * TT + cid - 1) * HW;
            #pragma unroll
            for (int k = 0; k < PXB / 256; k++) {
                int lp = k * 256 + tid;
                int p  = p0g + lp;
                int q  = b * HW + p;
                bool nw = false;
                float mv = msks[mrow + p];
                if (mv > MTHR && !g_topcov[q]) {
                    g_topval[q] = temps[mrow + p] * mv;  // goes UNDER existing
                    g_topcov[q] = 1;
                    nw = true;
                }
                unsigned m = __ballot_sync(0xffffffffu, nw);
                if ((tid & 31) == 0) sm.st.wm[tid >> 5] = m;
                __syncthreads();
                int off = base, tot = 0;
                #pragma unroll
                for (int w = 0; w < 8; w++) {
                    int c = __popc(sm.st.wm[w]);
                    if (w < (tid >> 5)) off += c;
                    tot += c;
                }
                if (nw) sm.st.list[off + __popc(m & ((1u << (tid & 31)) - 1))] = lp;
                base += tot;
                __syncthreads();
            }
        }
        const int n = base;

        if (s == NSTEP - 1) {
            // --- final composition for own pixels ---
            #pragma unroll
            for (int k = 0; k < PXB / 256; k++) {
                int p = p0g + k * 256 + tid;
                int q = b * HW + p;
                out[q] = g_topcov[q] ? g_topval[q] : bg[p];
            }
        } else {
            // --- gather-subtract D rows of own new pixels ---
            if (n > 0) {
                const int grp = tid >> 7;    // 0/1: even/odd list entries
                const int lt  = tid & 127;
                float a0 = 0.f, a1 = 0.f, a2 = 0.f, a3 = 0.f;
                if (lt < TT) {
                    const float* Db = g_D + ((size_t)b * HW + p0g) * TT + lt;
                    int j = grp;
                    for (; j + 6 < n; j += 8) {
                        a0 += Db[(size_t)sm.st.list[j    ] * TT];
                        a1 += Db[(size_t)sm.st.list[j + 2] * TT];
                        a2 += Db[(size_t)sm.st.list[j + 4] * TT];
                        a3 += Db[(size_t)sm.st.list[j + 6] * TT];
                    }
                    for (; j < n; j += 2) a0 += Db[(size_t)sm.st.list[j] * TT];
                    sm.st.partial[grp][lt] = (a0 + a1) + (a2 + a3);
                }
                __syncthreads();
                if (tid < TT) {
                    float tot2 = sm.st.partial[0][tid] + sm.st.partial[1][tid];
                    atomicAdd(&g_delta[b * TP1 + 1 + tid], -(double)tot2);
                }
            }
            grid_barrier(1 + s);
        }
    }
}

// ---------------------------------------------------------------------------
extern "C" void kernel_launch(void* const* d_in, const int* in_sizes, int n_in,
                              void* d_out, int out_size) {
    const float* x      = (const float*)d_in[0];   // (16,1,128,128)
    const float* temps  = (const float*)d_in[1];   // (16,96,1,128,128)
    const float* msks   = (const float*)d_in[2];   // (16,96,1,128,128)
    const float* bg     = (const float*)d_in[3];   // (1,128,128)
    float* out = (float*)d_out;                    // (16,1,128,128)

    k_init<<<1, 256>>>();
    k_all<<<NBLK, 256>>>(x, temps, msks, bg, out);
}